// round 11
// baseline (speedup 1.0000x reference)
#include <cuda_runtime.h>
#include <cuda_bf16.h>
#include <cstdint>

#define D 128
#define NMAX 100000
#define EMAX 3200000

#define SCAN_CHUNK 2048
#define MAX_CHUNKS ((NMAX + SCAN_CHUNK - 1) / SCAN_CHUNK)   // 49

__device__ float g_m1[(size_t)NMAX * D];
__device__ int   g_counts[NMAX];
__device__ int   g_row_start[NMAX + 1];
__device__ int   g_cursor[NMAX];
__device__ int2  g_edges[EMAX];   // .x = source-node idx, .y = val bits
__device__ int   g_chunk_sums[MAX_CHUNKS];
__device__ int   g_chunk_offs[MAX_CHUNKS];

// ---------------------------------------------------------------------------
// JAX threefry2x32, key=(0,42); confirmed: ctr=(hi=0, lo=i), bits = x0.
// ---------------------------------------------------------------------------
__device__ __forceinline__ unsigned int threefry_x0_k42(unsigned int ctr_lo) {
    unsigned int x0 = 0u;
    unsigned int x1 = ctr_lo;
    const unsigned int ks1 = 42u;
    const unsigned int ks2 = 42u ^ 0x1BD11BDAu;
    x1 += ks1;
#define TF_ROUND(r) { x0 += x1; x1 = __funnelshift_l(x1, x1, (r)); x1 ^= x0; }
    TF_ROUND(13) TF_ROUND(15) TF_ROUND(26) TF_ROUND(6)
    x0 += ks1; x1 += ks2 + 1u;
    TF_ROUND(17) TF_ROUND(29) TF_ROUND(16) TF_ROUND(24)
    x0 += ks2; x1 += 0u + 2u;
    TF_ROUND(13) TF_ROUND(15) TF_ROUND(26) TF_ROUND(6)
    x0 += 0u;  x1 += ks1 + 3u;
    TF_ROUND(17) TF_ROUND(29) TF_ROUND(16) TF_ROUND(24)
    x0 += ks1; x1 += ks2 + 4u;
    TF_ROUND(13) TF_ROUND(15) TF_ROUND(26) TF_ROUND(6)
    x0 += ks2;
#undef TF_ROUND
    return x0;
}

__device__ __forceinline__ float drop_one(float v, unsigned int i) {
    unsigned int bits = threefry_x0_k42(i);
    float u = __uint_as_float(0x3f800000u | (bits >> 9)) - 1.0f;
    return (u < 0.9f) ? (v * (1.0f / 0.9f)) : 0.0f;
}

// ---------------------------------------------------------------------------
// CSR build
// ---------------------------------------------------------------------------
__global__ void zero_counts_kernel(int N) {
    int i = blockIdx.x * blockDim.x + threadIdx.x;
    if (i < N) g_counts[i] = 0;
}

__global__ void hist_kernel(const int* __restrict__ row, int E) {
    int q = blockIdx.x * blockDim.x + threadIdx.x;
    int e0 = q * 4;
    if (e0 + 3 < E) {
        int4 r4 = reinterpret_cast<const int4*>(row)[q];
        atomicAdd(&g_counts[r4.x], 1);
        atomicAdd(&g_counts[r4.y], 1);
        atomicAdd(&g_counts[r4.z], 1);
        atomicAdd(&g_counts[r4.w], 1);
    } else {
        for (int e = e0; e < E; e++) atomicAdd(&g_counts[row[e]], 1);
    }
}

__global__ __launch_bounds__(1024)
void scan_reduce_kernel(int N) {
    __shared__ int sh[1024];
    int b = blockIdx.x, t = threadIdx.x;
    int i0 = b * SCAN_CHUNK + 2 * t;
    int s = 0;
    if (i0 < N)     s += g_counts[i0];
    if (i0 + 1 < N) s += g_counts[i0 + 1];
    sh[t] = s;
    __syncthreads();
    for (int off = 512; off > 0; off >>= 1) {
        if (t < off) sh[t] += sh[t + off];
        __syncthreads();
    }
    if (t == 0) g_chunk_sums[b] = sh[0];
}

__global__ void scan_sums_kernel(int nchunks) {
    if (threadIdx.x == 0) {
        int run = 0;
        for (int i = 0; i < nchunks; i++) { g_chunk_offs[i] = run; run += g_chunk_sums[i]; }
    }
}

__global__ __launch_bounds__(1024)
void scan_final_kernel(int N, int E) {
    __shared__ int sh[1024];
    int b = blockIdx.x, t = threadIdx.x;
    int i0 = b * SCAN_CHUNK + 2 * t;
    int c0 = (i0 < N)     ? g_counts[i0]     : 0;
    int c1 = (i0 + 1 < N) ? g_counts[i0 + 1] : 0;
    int pair = c0 + c1;
    sh[t] = pair;
    __syncthreads();
    for (int off = 1; off < 1024; off <<= 1) {
        int v = (t >= off) ? sh[t - off] : 0;
        __syncthreads();
        sh[t] += v;
        __syncthreads();
    }
    int excl = sh[t] - pair + g_chunk_offs[b];
    if (i0 < N)     { g_row_start[i0]     = excl;      g_cursor[i0]     = excl; }
    if (i0 + 1 < N) { g_row_start[i0 + 1] = excl + c0; g_cursor[i0 + 1] = excl + c0; }
    if (i0 == N - 1 || i0 + 1 == N - 1) g_row_start[N] = E;
}

__global__ void scatter_kernel(const int* __restrict__ row,
                               const int* __restrict__ col,
                               const float* __restrict__ vals,
                               const int* __restrict__ x, int E) {
    int e = blockIdx.x * blockDim.x + threadIdx.x;
    if (e >= E) return;
    int r = row[e];
    int pos = atomicAdd(&g_cursor[r], 1);
    g_edges[pos] = make_int2(x[col[e]], __float_as_int(vals[e]));
}

// ---------------------------------------------------------------------------
// Fused CSR SpMM + residual + dropout + e-copy (at L2 roofline)
// ---------------------------------------------------------------------------
__global__ __launch_bounds__(256)
void spmm_csr_kernel(const int* __restrict__ x,
                     const float* __restrict__ embed_w,
                     float* __restrict__ out, int N) {
    int warp = (blockIdx.x * blockDim.x + threadIdx.x) >> 5;
    if (warp >= N) return;
    int lane = threadIdx.x & 31;
    int r = warp;

    const float4* ew4 = reinterpret_cast<const float4*>(embed_w);

    float4 acc = ew4[(size_t)x[r] * 32 + lane];
    reinterpret_cast<float4*>(out)[(size_t)r * 64 + lane] = acc;

    int start = g_row_start[r];
    int end   = g_row_start[r + 1];

    for (int base = start; base < end; base += 32) {
        int j = base + lane;
        int  c = 0;
        float v = 0.0f;
        if (j < end) {
            int2 ed = g_edges[j];
            c = ed.x;
            v = __int_as_float(ed.y);
        }
        int m = min(32, end - base);
#pragma unroll 4
        for (int k = 0; k < m; k++) {
            int   ck = __shfl_sync(0xFFFFFFFFu, c, k);
            float vk = __shfl_sync(0xFFFFFFFFu, v, k);
            float4 ev = ew4[(size_t)ck * 32 + lane];
            acc.x += vk * ev.x;
            acc.y += vk * ev.y;
            acc.z += vk * ev.z;
            acc.w += vk * ev.w;
        }
    }

    unsigned int i0 = (unsigned int)r * 128u + (unsigned int)lane * 4u;
    acc.x = drop_one(acc.x, i0 + 0u);
    acc.y = drop_one(acc.y, i0 + 1u);
    acc.z = drop_one(acc.z, i0 + 2u);
    acc.w = drop_one(acc.w, i0 + 3u);

    reinterpret_cast<float4*>(g_m1)[(size_t)r * 32 + lane] = acc;
}

// ===========================================================================
// Tensor-core GEMM via warp-level mma.sync (bf16, compute_103-compatible):
// out[:,128:] = leaky_relu(m1 @ W^T + b)
// fp32 accuracy via bf16 split: D = Ahi@Whi + Ahi@Wlo + Alo@Whi.
// Smem: bf16 tiles, row stride 132 (264B) -> all fragment LDS.32 conflict-free.
// Block = 128 rows x 128 cols, 8 warps; warp = 16 rows, 16 n-tiles (m16n8k16).
// ===========================================================================

#define APITCH 264           // bytes per bf16 row (132 elems)
#define SM_AHI_OFF 0
#define SM_ALO_OFF 33792     // 128*264
#define SM_WHI_OFF 67584
#define SM_WLO_OFF 101376
#define SM_GEMM_TOTAL 135168

__device__ __forceinline__ uint32_t pack_bf16x2(float lo, float hi) {
    uint32_t r;
    asm("cvt.rn.bf16x2.f32 %0, %1, %2;" : "=r"(r) : "f"(hi), "f"(lo));
    return r;
}
__device__ __forceinline__ float bf16_round(float x) {
    return __bfloat162float(__float2bfloat16_rn(x));
}
__device__ __forceinline__ void mma16816(float* c, const uint32_t* a,
                                         uint32_t b0, uint32_t b1) {
    asm volatile(
        "mma.sync.aligned.m16n8k16.row.col.f32.bf16.bf16.f32 "
        "{%0,%1,%2,%3}, {%4,%5,%6,%7}, {%8,%9}, {%0,%1,%2,%3};"
        : "+f"(c[0]), "+f"(c[1]), "+f"(c[2]), "+f"(c[3])
        : "r"(a[0]), "r"(a[1]), "r"(a[2]), "r"(a[3]), "r"(b0), "r"(b1));
}

__global__ __launch_bounds__(256)
void gemm_mma_kernel(const float* __restrict__ W,
                     const float* __restrict__ bias,
                     float* __restrict__ out, int N) {
    extern __shared__ __align__(16) char smem[];
    const int t    = threadIdx.x;
    const int brow = blockIdx.x * 128;

    // ---- convert A (this block's m1 rows) and W to bf16 hi/lo in smem ----
    {
        int r = t >> 1, h = t & 1;           // row 0..127, half 0..1 (64 cols)
        int gr = brow + r;
        const float4* arow =
            reinterpret_cast<const float4*>(g_m1 + (size_t)gr * D) + h * 16;
        const float4* wrow =
            reinterpret_cast<const float4*>(W + (size_t)r * D) + h * 16;
#pragma unroll
        for (int i = 0; i < 16; i++) {
            int c = h * 64 + i * 4;
            uint32_t off = (uint32_t)r * APITCH + (uint32_t)c * 2;
            // A
            float4 f = make_float4(0.f, 0.f, 0.f, 0.f);
            if (gr < N) f = arow[i];
            float hx = bf16_round(f.x), hy = bf16_round(f.y);
            float hz = bf16_round(f.z), hw = bf16_round(f.w);
            *reinterpret_cast<uint32_t*>(smem + SM_AHI_OFF + off)     = pack_bf16x2(f.x, f.y);
            *reinterpret_cast<uint32_t*>(smem + SM_AHI_OFF + off + 4) = pack_bf16x2(f.z, f.w);
            *reinterpret_cast<uint32_t*>(smem + SM_ALO_OFF + off)     = pack_bf16x2(f.x - hx, f.y - hy);
            *reinterpret_cast<uint32_t*>(smem + SM_ALO_OFF + off + 4) = pack_bf16x2(f.z - hz, f.w - hw);
            // W
            float4 g = wrow[i];
            float gx = bf16_round(g.x), gy = bf16_round(g.y);
            float gz = bf16_round(g.z), gw = bf16_round(g.w);
            *reinterpret_cast<uint32_t*>(smem + SM_WHI_OFF + off)     = pack_bf16x2(g.x, g.y);
            *reinterpret_cast<uint32_t*>(smem + SM_WHI_OFF + off + 4) = pack_bf16x2(g.z, g.w);
            *reinterpret_cast<uint32_t*>(smem + SM_WLO_OFF + off)     = pack_bf16x2(g.x - gx, g.y - gy);
            *reinterpret_cast<uint32_t*>(smem + SM_WLO_OFF + off + 4) = pack_bf16x2(g.z - gz, g.w - gw);
        }
    }
    __syncthreads();

    // ---- mma mainloop ----
    const int w    = t >> 5;        // warp 0..7 -> rows w*16..w*16+15
    const int lane = t & 31;
    const int g    = lane >> 2;     // group row / B col
    const int tq   = lane & 3;

    float acc[16][4];
#pragma unroll
    for (int n = 0; n < 16; n++)
#pragma unroll
        for (int q = 0; q < 4; q++) acc[n][q] = 0.0f;

    const uint32_t a_row0 = (uint32_t)(w * 16 + g) * APITCH + tq * 4;

#pragma unroll
    for (int k0 = 0; k0 < 128; k0 += 16) {
        uint32_t abase = a_row0 + k0 * 2;
        uint32_t ah[4], al[4];
        ah[0] = *reinterpret_cast<const uint32_t*>(smem + SM_AHI_OFF + abase);
        ah[1] = *reinterpret_cast<const uint32_t*>(smem + SM_AHI_OFF + abase + 8 * APITCH);
        ah[2] = *reinterpret_cast<const uint32_t*>(smem + SM_AHI_OFF + abase + 16);
        ah[3] = *reinterpret_cast<const uint32_t*>(smem + SM_AHI_OFF + abase + 8 * APITCH + 16);
        al[0] = *reinterpret_cast<const uint32_t*>(smem + SM_ALO_OFF + abase);
        al[1] = *reinterpret_cast<const uint32_t*>(smem + SM_ALO_OFF + abase + 8 * APITCH);
        al[2] = *reinterpret_cast<const uint32_t*>(smem + SM_ALO_OFF + abase + 16);
        al[3] = *reinterpret_cast<const uint32_t*>(smem + SM_ALO_OFF + abase + 8 * APITCH + 16);
#pragma unroll
        for (int n = 0; n < 16; n++) {
            uint32_t bbase = (uint32_t)(n * 8 + g) * APITCH + k0 * 2 + tq * 4;
            uint32_t bh0 = *reinterpret_cast<const uint32_t*>(smem + SM_WHI_OFF + bbase);
            uint32_t bh1 = *reinterpret_cast<const uint32_t*>(smem + SM_WHI_OFF + bbase + 16);
            uint32_t bl0 = *reinterpret_cast<const uint32_t*>(smem + SM_WLO_OFF + bbase);
            uint32_t bl1 = *reinterpret_cast<const uint32_t*>(smem + SM_WLO_OFF + bbase + 16);
            mma16816(acc[n], ah, bh0, bh1);
            mma16816(acc[n], ah, bl0, bl1);
            mma16816(acc[n], al, bh0, bh1);
        }
    }

    // ---- epilogue: bias + leaky relu + store ----
    int row0 = brow + w * 16 + g;
    int row1 = row0 + 8;
#pragma unroll
    for (int n = 0; n < 16; n++) {
        int c = n * 8 + tq * 2;
        float2 bv = *reinterpret_cast<const float2*>(bias + c);
        float y0 = acc[n][0] + bv.x;
        float y1 = acc[n][1] + bv.y;
        float y2 = acc[n][2] + bv.x;
        float y3 = acc[n][3] + bv.y;
        y0 = (y0 >= 0.f) ? y0 : 0.2f * y0;
        y1 = (y1 >= 0.f) ? y1 : 0.2f * y1;
        y2 = (y2 >= 0.f) ? y2 : 0.2f * y2;
        y3 = (y3 >= 0.f) ? y3 : 0.2f * y3;
        if (row0 < N)
            *reinterpret_cast<float2*>(out + (size_t)row0 * 256 + 128 + c) = make_float2(y0, y1);
        if (row1 < N)
            *reinterpret_cast<float2*>(out + (size_t)row1 * 256 + 128 + c) = make_float2(y2, y3);
    }
}

// ---------------------------------------------------------------------------
extern "C" void kernel_launch(void* const* d_in, const int* in_sizes, int n_in,
                              void* d_out, int out_size) {
    const int*   x       = (const int*)d_in[0];
    const int*   row     = (const int*)d_in[1];
    const int*   col     = (const int*)d_in[2];
    const float* vals    = (const float*)d_in[3];
    const float* embed_w = (const float*)d_in[4];
    const float* fc_w    = (const float*)d_in[5];
    const float* fc_b    = (const float*)d_in[6];
    float* out = (float*)d_out;

    const int N = in_sizes[0];
    const int E = in_sizes[1];
    const int nchunks = (N + SCAN_CHUNK - 1) / SCAN_CHUNK;

    cudaFuncSetAttribute(gemm_mma_kernel,
                         cudaFuncAttributeMaxDynamicSharedMemorySize, SM_GEMM_TOTAL);

    zero_counts_kernel<<<(N + 255) / 256, 256>>>(N);
    hist_kernel<<<((E + 3) / 4 + 255) / 256, 256>>>(row, E);
    scan_reduce_kernel<<<nchunks, 1024>>>(N);
    scan_sums_kernel<<<1, 32>>>(nchunks);
    scan_final_kernel<<<nchunks, 1024>>>(N, E);
    scatter_kernel<<<(E + 255) / 256, 256>>>(row, col, vals, x, E);

    spmm_csr_kernel<<<(N * 32 + 255) / 256, 256>>>(x, embed_w, out, N);

    gemm_mma_kernel<<<(N + 127) / 128, 256, SM_GEMM_TOTAL>>>(fc_w, fc_b, out, N);
}